// round 2
// baseline (speedup 1.0000x reference)
#include <cuda_runtime.h>
#include <math.h>

#define BN    8192      // B*N nodes
#define HID   128
#define NE    262144
#define NRBF  64
#define NBLK  4
#define TLEN  8192      // filter table resolution
#define RCUTF 6.0f
#define GAMMAF (10.0f/36.0f)

// ---- scratch (device globals: allocation-free) ----
__device__ float g_h[BN * HID];          // node features
__device__ float g_x[BN * HID];          // h @ lin_in
__device__ float g_agg[BN * HID];        // scatter-add accumulator
__device__ float g_u[NE];                // scaled table coordinate per edge
__device__ float g_table[NBLK * TLEN * HID];  // tabulated edge filter w_i(d)

__device__ __forceinline__ float silu_f(float v) { return v / (1.0f + expf(-v)); }

// ---------------------------------------------------------------- embed
__global__ void k_embed(const int* __restrict__ Z, const float* __restrict__ embed_w) {
    int n = blockIdx.x, j = threadIdx.x;
    g_h[n * HID + j] = embed_w[Z[n] * HID + j];
}

// ---------------------------------------------------------------- edge distances -> table coord
__global__ void k_dist(const int* __restrict__ ei, const float* __restrict__ pos) {
    int e = blockIdx.x * blockDim.x + threadIdx.x;
    if (e >= NE) return;
    int s = ei[e], d = ei[NE + e];
    float dx = pos[3*s]   - pos[3*d];
    float dy = pos[3*s+1] - pos[3*d+1];
    float dz = pos[3*s+2] - pos[3*d+2];
    float dd = sqrtf(dx*dx + dy*dy + dz*dz);
    dd = fminf(dd, RCUTF);
    g_u[e] = dd * ((float)(TLEN - 1) / RCUTF);
}

// ---------------------------------------------------------------- build w_i(d) tables
// grid (TLEN/32, NBLK), block 128, dyn smem = (NRBF+HID)*HID floats
__global__ void k_table(const float* __restrict__ w1, const float* __restrict__ b1,
                        const float* __restrict__ w2, const float* __restrict__ b2) {
    extern __shared__ float sm[];
    float* W1s = sm;                 // 64*128
    float* W2s = sm + NRBF * HID;    // 128*128
    __shared__ float rbf[NRBF];
    __shared__ float hidb[HID];
    int blk = blockIdx.y;
    int t0  = blockIdx.x * 32;
    int j   = threadIdx.x;

    const float* W1 = w1 + blk * NRBF * HID;
    const float* W2 = w2 + blk * HID * HID;
    for (int k = j; k < NRBF * HID; k += HID) W1s[k] = W1[k];
    for (int k = j; k < HID * HID;  k += HID) W2s[k] = W2[k];
    float bb1 = b1[blk * HID + j];
    float bb2 = b2[blk * HID + j];
    __syncthreads();

    for (int tt = 0; tt < 32; tt++) {
        int t = t0 + tt;
        float d = (float)t * (RCUTF / (float)(TLEN - 1));
        if (j < NRBF) {
            float uu = d - (float)j * (RCUTF / (float)(NRBF - 1));
            rbf[j] = expf(-GAMMAF * uu * uu);
        }
        __syncthreads();                       // sync A
        float acc = bb1;
        #pragma unroll 8
        for (int k = 0; k < NRBF; k++) acc += rbf[k] * W1s[k * HID + j];
        float hv = silu_f(acc);
        hidb[j] = hv;
        __syncthreads();                       // sync B
        float acc2 = bb2;
        #pragma unroll 8
        for (int k = 0; k < HID; k++) acc2 += hidb[k] * W2s[k * HID + j];
        g_table[(blk * TLEN + t) * HID + j] = acc2;
    }
}

// ---------------------------------------------------------------- x = h @ lin_in, zero agg
// grid BN/16, block 128, dyn smem = HID*HID floats
__global__ void k_xgemm(const float* __restrict__ W) {
    extern __shared__ float Ws[];
    __shared__ float hr[HID];
    int j = threadIdx.x;
    for (int k = j; k < HID * HID; k += HID) Ws[k] = W[k];
    __syncthreads();
    int row0 = blockIdx.x * 16;
    for (int r = 0; r < 16; r++) {
        int row = row0 + r;
        hr[j] = g_h[row * HID + j];
        __syncthreads();
        float acc = 0.0f;
        #pragma unroll 8
        for (int k = 0; k < HID; k++) acc += hr[k] * Ws[k * HID + j];
        g_x[row * HID + j]   = acc;
        g_agg[row * HID + j] = 0.0f;
        __syncthreads();
    }
}

// ---------------------------------------------------------------- edge scatter (warp per edge)
__global__ void k_edge(const int* __restrict__ ei, int blk) {
    int gid  = blockIdx.x * blockDim.x + threadIdx.x;
    int e    = gid >> 5;
    int lane = gid & 31;
    if (e >= NE) return;
    float u = g_u[e];
    int i0 = (int)u;
    if (i0 > TLEN - 2) i0 = TLEN - 2;
    float f = u - (float)i0;
    int s = ei[e], d = ei[NE + e];
    const float4* t0 = (const float4*)(g_table + (size_t)(blk * TLEN + i0) * HID);
    float4 a = t0[lane];
    float4 b = t0[32 + lane];
    const float4* xp = (const float4*)(g_x + (size_t)s * HID);
    float4 xv = xp[lane];
    float* ag = g_agg + (size_t)d * HID + lane * 4;
    atomicAdd(ag + 0, (a.x + f * (b.x - a.x)) * xv.x);
    atomicAdd(ag + 1, (a.y + f * (b.y - a.y)) * xv.y);
    atomicAdd(ag + 2, (a.z + f * (b.z - a.z)) * xv.z);
    atomicAdd(ag + 3, (a.w + f * (b.w - a.w)) * xv.w);
}

// ---------------------------------------------------------------- node MLP + residual + LN
// grid BN/16, block 128, dyn smem = 2*HID*HID floats
__global__ void k_node(const float* __restrict__ W1, const float* __restrict__ B1,
                       const float* __restrict__ W2, const float* __restrict__ B2,
                       const float* __restrict__ G,  const float* __restrict__ Bt) {
    extern __shared__ float sm[];
    float* W1s = sm;
    float* W2s = sm + HID * HID;
    __shared__ float buf[HID];
    __shared__ float red[8];
    int j = threadIdx.x;
    for (int k = j; k < HID * HID; k += HID) { W1s[k] = W1[k]; W2s[k] = W2[k]; }
    float b1 = B1[j], b2 = B2[j], gg = G[j], bb = Bt[j];
    __syncthreads();

    int row0 = blockIdx.x * 16;
    for (int r = 0; r < 16; r++) {
        int row = row0 + r;
        buf[j] = g_agg[row * HID + j];
        __syncthreads();
        float a = b1;
        #pragma unroll 8
        for (int k = 0; k < HID; k++) a += buf[k] * W1s[k * HID + j];
        a = silu_f(a);
        __syncthreads();
        buf[j] = a;
        __syncthreads();
        float o = b2;
        #pragma unroll 8
        for (int k = 0; k < HID; k++) o += buf[k] * W2s[k * HID + j];
        float y = g_h[row * HID + j] + o;

        // layernorm over 128 channels
        float s = y, q = y * y;
        #pragma unroll
        for (int off = 16; off > 0; off >>= 1) {
            s += __shfl_down_sync(0xffffffffu, s, off);
            q += __shfl_down_sync(0xffffffffu, q, off);
        }
        if ((j & 31) == 0) { red[j >> 5] = s; red[4 + (j >> 5)] = q; }
        __syncthreads();
        float S = red[0] + red[1] + red[2] + red[3];
        float Q = red[4] + red[5] + red[6] + red[7];
        float mu  = S * (1.0f / HID);
        float var = Q * (1.0f / HID) - mu * mu;
        float rstd = rsqrtf(var + 1e-5f);
        g_h[row * HID + j] = (y - mu) * rstd * gg + bb;
        __syncthreads();
    }
}

// ---------------------------------------------------------------- output zero + readout
__global__ void k_zero_out(float* out) {
    if (threadIdx.x < 64) out[threadIdx.x] = 0.0f;
}

__global__ void k_readout(const float* __restrict__ w1, const float* __restrict__ b1v,
                          const float* __restrict__ w2, const float* __restrict__ b2v,
                          float* __restrict__ out) {
    __shared__ float s[HID];
    __shared__ float part[2];
    int n = blockIdx.x, t = threadIdx.x;   // 64 threads
    float h0 = g_h[n * HID + t];
    float h1 = g_h[n * HID + 64 + t];
    s[t]      = silu_f(h0);
    s[64 + t] = silu_f(h1);
    __syncthreads();
    float a = b1v[t];
    #pragma unroll 8
    for (int k = 0; k < HID; k++) a += s[k] * w1[k * 64 + t];
    float v = silu_f(a) * w2[t];
    #pragma unroll
    for (int off = 16; off > 0; off >>= 1) v += __shfl_down_sync(0xffffffffu, v, off);
    if ((t & 31) == 0) part[t >> 5] = v;
    __syncthreads();
    if (t == 0) atomicAdd(&out[n >> 7], part[0] + part[1] + b2v[0]);
}

// ---------------------------------------------------------------- launch
extern "C" void kernel_launch(void* const* d_in, const int* in_sizes, int n_in,
                              void* d_out, int out_size) {
    const int*   Z       = (const int*)  d_in[0];
    const float* pos     = (const float*)d_in[1];
    const int*   ei      = (const int*)  d_in[2];
    const float* embed_w = (const float*)d_in[3];
    const float* ew1     = (const float*)d_in[4];
    const float* eb1     = (const float*)d_in[5];
    const float* ew2     = (const float*)d_in[6];
    const float* eb2     = (const float*)d_in[7];
    const float* linw    = (const float*)d_in[8];
    const float* nw1     = (const float*)d_in[9];
    const float* nb1     = (const float*)d_in[10];
    const float* nw2     = (const float*)d_in[11];
    const float* nb2     = (const float*)d_in[12];
    const float* lng     = (const float*)d_in[13];
    const float* lnb     = (const float*)d_in[14];
    const float* row1    = (const float*)d_in[15];
    const float* rob1    = (const float*)d_in[16];
    const float* row2    = (const float*)d_in[17];
    const float* rob2    = (const float*)d_in[18];
    float* out = (float*)d_out;

    cudaFuncSetAttribute(k_table, cudaFuncAttributeMaxDynamicSharedMemorySize,
                         (NRBF + HID) * HID * (int)sizeof(float));
    cudaFuncSetAttribute(k_xgemm, cudaFuncAttributeMaxDynamicSharedMemorySize,
                         HID * HID * (int)sizeof(float));
    cudaFuncSetAttribute(k_node, cudaFuncAttributeMaxDynamicSharedMemorySize,
                         2 * HID * HID * (int)sizeof(float));

    k_embed<<<BN, HID>>>(Z, embed_w);
    k_dist<<<(NE + 255) / 256, 256>>>(ei, pos);
    dim3 tg(TLEN / 32, NBLK);
    k_table<<<tg, HID, (NRBF + HID) * HID * sizeof(float)>>>(ew1, eb1, ew2, eb2);

    for (int b = 0; b < NBLK; b++) {
        k_xgemm<<<BN / 16, HID, HID * HID * sizeof(float)>>>(linw + b * HID * HID);
        k_edge<<<NE / 8, 256>>>(ei, b);
        k_node<<<BN / 16, HID, 2 * HID * HID * sizeof(float)>>>(
            nw1 + b * HID * HID, nb1 + b * HID,
            nw2 + b * HID * HID, nb2 + b * HID,
            lng + b * HID, lnb + b * HID);
    }

    k_zero_out<<<1, 64>>>(out);
    k_readout<<<BN, 64>>>(row1, rob1, row2, rob2, out);
}

// round 3
// speedup vs baseline: 3.7382x; 3.7382x over previous
#include <cuda_runtime.h>
#include <math.h>

#define BN    8192      // B*N nodes
#define HID   128
#define NE    262144
#define NRBF  64
#define NBLK  4
#define TLEN  2048      // filter table resolution (interp err ~2.6e-6 rel)
#define RCUTF 6.0f
#define GAMMAF (10.0f/36.0f)

// ---- scratch (device globals: allocation-free) ----
__device__ float g_h[BN * HID];
__device__ float g_x[BN * HID];
__device__ float g_agg[BN * HID];
__device__ float g_u[NE];
__device__ float g_table[NBLK * TLEN * HID];   // 4 MB — L2-resident

__device__ __forceinline__ float silu_f(float v) { return v / (1.0f + expf(-v)); }

// ---------------------------------------------------------------- embed
__global__ void k_embed(const int* __restrict__ Z, const float* __restrict__ embed_w) {
    int n = blockIdx.x, j = threadIdx.x;
    g_h[n * HID + j] = embed_w[Z[n] * HID + j];
}

// ---------------------------------------------------------------- distances -> table coord
__global__ void k_dist(const int* __restrict__ ei, const float* __restrict__ pos) {
    int e = blockIdx.x * blockDim.x + threadIdx.x;
    if (e >= NE) return;
    int s = ei[e], d = ei[NE + e];
    float dx = pos[3*s]   - pos[3*d];
    float dy = pos[3*s+1] - pos[3*d+1];
    float dz = pos[3*s+2] - pos[3*d+2];
    float dd = sqrtf(dx*dx + dy*dy + dz*dz);
    dd = fminf(dd, RCUTF);
    g_u[e] = dd * ((float)(TLEN - 1) / RCUTF);
}

// ================================================================
// Register-tiled GEMM helpers: block = 256 threads, tile = 64 rows x 128 cols,
// thread tile = 4 rows x 8 cols.  cg = tid&15 (cols cg*8..+7), rg = tid>>4 (rows rg*4..+3)
// ================================================================

// ---------------------------------------------------------------- tables: w_i(d) for d-grid
// grid (TLEN/64, NBLK), block 256
// smem: rbf[64*64] + act[64*128] + Ws[128*128]
__global__ void k_table_f(const float* __restrict__ w1, const float* __restrict__ b1,
                          const float* __restrict__ w2, const float* __restrict__ b2) {
    extern __shared__ float sm[];
    float* rbfs = sm;                 // 64*64
    float* act  = sm + 64*64;         // 64*128
    float* Ws   = sm + 64*64 + 64*128;// 128*128
    int tid = threadIdx.x;
    int blk = blockIdx.y;
    int t0  = blockIdx.x * 64;
    const float DSTEP = RCUTF / (float)(TLEN - 1);
    const float CSTEP = RCUTF / (float)(NRBF - 1);

    for (int i = tid; i < 64 * 64; i += 256) {
        int row = i >> 6, c = i & 63;
        float d = (float)(t0 + row) * DSTEP;
        float u = d - (float)c * CSTEP;
        rbfs[i] = expf(-GAMMAF * u * u);
    }
    {   // load W1 [64 x 128]
        const float4* W4 = (const float4*)(w1 + blk * NRBF * HID);
        float4* Ws4 = (float4*)Ws;
        for (int i = tid; i < NRBF * 32; i += 256) Ws4[i] = W4[i];
    }
    __syncthreads();

    int cg = tid & 15, rg = tid >> 4;
    float acc[4][8];
    #pragma unroll
    for (int r = 0; r < 4; r++)
        #pragma unroll
        for (int c = 0; c < 8; c++) acc[r][c] = 0.0f;

    #pragma unroll 4
    for (int k = 0; k < NRBF; k++) {
        float4 w0 = ((const float4*)(Ws + k * 128))[cg * 2];
        float4 w1v = ((const float4*)(Ws + k * 128))[cg * 2 + 1];
        #pragma unroll
        for (int r = 0; r < 4; r++) {
            float a = rbfs[(rg * 4 + r) * 64 + k];
            acc[r][0] += a * w0.x;  acc[r][1] += a * w0.y;
            acc[r][2] += a * w0.z;  acc[r][3] += a * w0.w;
            acc[r][4] += a * w1v.x; acc[r][5] += a * w1v.y;
            acc[r][6] += a * w1v.z; acc[r][7] += a * w1v.w;
        }
    }
    float bb[8];
    #pragma unroll
    for (int c = 0; c < 8; c++) bb[c] = __ldg(&b1[blk * HID + cg * 8 + c]);
    #pragma unroll
    for (int r = 0; r < 4; r++)
        #pragma unroll
        for (int c = 0; c < 8; c++)
            act[(rg * 4 + r) * 128 + cg * 8 + c] = silu_f(acc[r][c] + bb[c]);
    __syncthreads();
    {   // load W2 [128 x 128]
        const float4* W4 = (const float4*)(w2 + blk * HID * HID);
        float4* Ws4 = (float4*)Ws;
        for (int i = tid; i < HID * 32; i += 256) Ws4[i] = W4[i];
    }
    __syncthreads();

    #pragma unroll
    for (int r = 0; r < 4; r++)
        #pragma unroll
        for (int c = 0; c < 8; c++) acc[r][c] = 0.0f;
    #pragma unroll 4
    for (int k = 0; k < HID; k++) {
        float4 w0 = ((const float4*)(Ws + k * 128))[cg * 2];
        float4 w1v = ((const float4*)(Ws + k * 128))[cg * 2 + 1];
        #pragma unroll
        for (int r = 0; r < 4; r++) {
            float a = act[(rg * 4 + r) * 128 + k];
            acc[r][0] += a * w0.x;  acc[r][1] += a * w0.y;
            acc[r][2] += a * w0.z;  acc[r][3] += a * w0.w;
            acc[r][4] += a * w1v.x; acc[r][5] += a * w1v.y;
            acc[r][6] += a * w1v.z; acc[r][7] += a * w1v.w;
        }
    }
    #pragma unroll
    for (int c = 0; c < 8; c++) bb[c] = __ldg(&b2[blk * HID + cg * 8 + c]);
    #pragma unroll
    for (int r = 0; r < 4; r++) {
        float* dst = g_table + (size_t)(blk * TLEN + t0 + rg * 4 + r) * HID + cg * 8;
        float4 o0 = {acc[r][0] + bb[0], acc[r][1] + bb[1], acc[r][2] + bb[2], acc[r][3] + bb[3]};
        float4 o1 = {acc[r][4] + bb[4], acc[r][5] + bb[5], acc[r][6] + bb[6], acc[r][7] + bb[7]};
        ((float4*)dst)[0] = o0;
        ((float4*)dst)[1] = o1;
    }
}

// ---------------------------------------------------------------- x = h @ lin_in ; zero agg
// grid BN/64, block 256; smem: hs[64*128] + Ws[128*128]
__global__ void k_xgemm_f(const float* __restrict__ W) {
    extern __shared__ float sm[];
    float* hs = sm;                   // 64*128
    float* Ws = sm + 64 * 128;        // 128*128
    int tid = threadIdx.x;
    int row0 = blockIdx.x * 64;
    {
        const float4* s4 = (const float4*)(g_h + (size_t)row0 * HID);
        float4* d4 = (float4*)hs;
        for (int i = tid; i < 64 * 32; i += 256) d4[i] = s4[i];
        const float4* W4 = (const float4*)W;
        float4* Ws4 = (float4*)Ws;
        for (int i = tid; i < HID * 32; i += 256) Ws4[i] = W4[i];
    }
    __syncthreads();

    int cg = tid & 15, rg = tid >> 4;
    float acc[4][8];
    #pragma unroll
    for (int r = 0; r < 4; r++)
        #pragma unroll
        for (int c = 0; c < 8; c++) acc[r][c] = 0.0f;

    #pragma unroll 4
    for (int k = 0; k < HID; k++) {
        float4 w0 = ((const float4*)(Ws + k * 128))[cg * 2];
        float4 w1v = ((const float4*)(Ws + k * 128))[cg * 2 + 1];
        #pragma unroll
        for (int r = 0; r < 4; r++) {
            float a = hs[(rg * 4 + r) * 128 + k];
            acc[r][0] += a * w0.x;  acc[r][1] += a * w0.y;
            acc[r][2] += a * w0.z;  acc[r][3] += a * w0.w;
            acc[r][4] += a * w1v.x; acc[r][5] += a * w1v.y;
            acc[r][6] += a * w1v.z; acc[r][7] += a * w1v.w;
        }
    }
    #pragma unroll
    for (int r = 0; r < 4; r++) {
        float* dst = g_x + (size_t)(row0 + rg * 4 + r) * HID + cg * 8;
        float4 o0 = {acc[r][0], acc[r][1], acc[r][2], acc[r][3]};
        float4 o1 = {acc[r][4], acc[r][5], acc[r][6], acc[r][7]};
        ((float4*)dst)[0] = o0;
        ((float4*)dst)[1] = o1;
    }
    // zero agg tile
    float4 z = {0.f, 0.f, 0.f, 0.f};
    float4* ag4 = (float4*)(g_agg + (size_t)row0 * HID);
    for (int i = tid; i < 64 * 32; i += 256) ag4[i] = z;
}

// ---------------------------------------------------------------- edge scatter (warp/edge, v4 red)
__global__ void k_edge(const int* __restrict__ ei, int blk) {
    int gid  = blockIdx.x * blockDim.x + threadIdx.x;
    int e    = gid >> 5;
    int lane = gid & 31;
    if (e >= NE) return;
    float u = __ldg(&g_u[e]);
    int i0 = (int)u;
    if (i0 > TLEN - 2) i0 = TLEN - 2;
    float f = u - (float)i0;
    int s = __ldg(&ei[e]), d = __ldg(&ei[NE + e]);
    const float4* t0 = (const float4*)(g_table + (size_t)(blk * TLEN + i0) * HID);
    float4 a = __ldg(&t0[lane]);
    float4 b = __ldg(&t0[32 + lane]);
    float4 xv = __ldg(&((const float4*)(g_x + (size_t)s * HID))[lane]);
    float m0 = (a.x + f * (b.x - a.x)) * xv.x;
    float m1 = (a.y + f * (b.y - a.y)) * xv.y;
    float m2 = (a.z + f * (b.z - a.z)) * xv.z;
    float m3 = (a.w + f * (b.w - a.w)) * xv.w;
    float* ag = g_agg + (size_t)d * HID + lane * 4;
    asm volatile("red.global.add.v4.f32 [%0], {%1, %2, %3, %4};"
                 :: "l"(ag), "f"(m0), "f"(m1), "f"(m2), "f"(m3) : "memory");
}

// ---------------------------------------------------------------- fused node MLP + residual + LN
// grid BN/64, block 256; smem: ins[64*128] + act[64*128] + Ws[128*128]
__global__ void k_node_f(const float* __restrict__ W1, const float* __restrict__ B1,
                         const float* __restrict__ W2, const float* __restrict__ B2,
                         const float* __restrict__ G,  const float* __restrict__ Bt) {
    extern __shared__ float sm[];
    float* ins = sm;                    // 64*128: agg tile, later y tile
    float* act = sm + 64 * 128;         // 64*128
    float* Ws  = sm + 2 * 64 * 128;     // 128*128
    int tid = threadIdx.x;
    int row0 = blockIdx.x * 64;
    {
        const float4* s4 = (const float4*)(g_agg + (size_t)row0 * HID);
        float4* d4 = (float4*)ins;
        for (int i = tid; i < 64 * 32; i += 256) d4[i] = s4[i];
        const float4* W4 = (const float4*)W1;
        float4* Ws4 = (float4*)Ws;
        for (int i = tid; i < HID * 32; i += 256) Ws4[i] = W4[i];
    }
    __syncthreads();

    int cg = tid & 15, rg = tid >> 4;
    float acc[4][8];
    #pragma unroll
    for (int r = 0; r < 4; r++)
        #pragma unroll
        for (int c = 0; c < 8; c++) acc[r][c] = 0.0f;

    #pragma unroll 4
    for (int k = 0; k < HID; k++) {
        float4 w0 = ((const float4*)(Ws + k * 128))[cg * 2];
        float4 w1v = ((const float4*)(Ws + k * 128))[cg * 2 + 1];
        #pragma unroll
        for (int r = 0; r < 4; r++) {
            float a = ins[(rg * 4 + r) * 128 + k];
            acc[r][0] += a * w0.x;  acc[r][1] += a * w0.y;
            acc[r][2] += a * w0.z;  acc[r][3] += a * w0.w;
            acc[r][4] += a * w1v.x; acc[r][5] += a * w1v.y;
            acc[r][6] += a * w1v.z; acc[r][7] += a * w1v.w;
        }
    }
    float bb[8];
    #pragma unroll
    for (int c = 0; c < 8; c++) bb[c] = __ldg(&B1[cg * 8 + c]);
    #pragma unroll
    for (int r = 0; r < 4; r++)
        #pragma unroll
        for (int c = 0; c < 8; c++)
            act[(rg * 4 + r) * 128 + cg * 8 + c] = silu_f(acc[r][c] + bb[c]);
    __syncthreads();
    {
        const float4* W4 = (const float4*)W2;
        float4* Ws4 = (float4*)Ws;
        for (int i = tid; i < HID * 32; i += 256) Ws4[i] = W4[i];
    }
    __syncthreads();

    #pragma unroll
    for (int r = 0; r < 4; r++)
        #pragma unroll
        for (int c = 0; c < 8; c++) acc[r][c] = 0.0f;
    #pragma unroll 4
    for (int k = 0; k < HID; k++) {
        float4 w0 = ((const float4*)(Ws + k * 128))[cg * 2];
        float4 w1v = ((const float4*)(Ws + k * 128))[cg * 2 + 1];
        #pragma unroll
        for (int r = 0; r < 4; r++) {
            float a = act[(rg * 4 + r) * 128 + k];
            acc[r][0] += a * w0.x;  acc[r][1] += a * w0.y;
            acc[r][2] += a * w0.z;  acc[r][3] += a * w0.w;
            acc[r][4] += a * w1v.x; acc[r][5] += a * w1v.y;
            acc[r][6] += a * w1v.z; acc[r][7] += a * w1v.w;
        }
    }
    #pragma unroll
    for (int c = 0; c < 8; c++) bb[c] = __ldg(&B2[cg * 8 + c]);
    // y = h + out, staged into ins for the LN pass
    #pragma unroll
    for (int r = 0; r < 4; r++) {
        int row = row0 + rg * 4 + r;
        const float* hp = g_h + (size_t)row * HID + cg * 8;
        #pragma unroll
        for (int c = 0; c < 8; c++)
            ins[(rg * 4 + r) * 128 + cg * 8 + c] = acc[r][c] + bb[c] + __ldg(&hp[c]);
    }
    __syncthreads();

    // layernorm: 4 threads per row, 32 cols each
    int r = tid >> 2, q = tid & 3;
    const float4* yr = (const float4*)(ins + r * 128 + q * 32);
    float s = 0.0f, ssq = 0.0f;
    float4 v[8];
    #pragma unroll
    for (int i = 0; i < 8; i++) {
        v[i] = yr[i];
        s   += v[i].x + v[i].y + v[i].z + v[i].w;
        ssq += v[i].x * v[i].x + v[i].y * v[i].y + v[i].z * v[i].z + v[i].w * v[i].w;
    }
    s   += __shfl_xor_sync(0xffffffffu, s, 1);
    ssq += __shfl_xor_sync(0xffffffffu, ssq, 1);
    s   += __shfl_xor_sync(0xffffffffu, s, 2);
    ssq += __shfl_xor_sync(0xffffffffu, ssq, 2);
    float mu = s * (1.0f / HID);
    float var = ssq * (1.0f / HID) - mu * mu;
    float rstd = rsqrtf(var + 1e-5f);
    float4* outp = (float4*)(g_h + (size_t)(row0 + r) * HID + q * 32);
    const float4* G4 = (const float4*)(G + q * 32);
    const float4* B4 = (const float4*)(Bt + q * 32);
    #pragma unroll
    for (int i = 0; i < 8; i++) {
        float4 gv = __ldg(&G4[i]);
        float4 bv = __ldg(&B4[i]);
        float4 o;
        o.x = (v[i].x - mu) * rstd * gv.x + bv.x;
        o.y = (v[i].y - mu) * rstd * gv.y + bv.y;
        o.z = (v[i].z - mu) * rstd * gv.z + bv.z;
        o.w = (v[i].w - mu) * rstd * gv.w + bv.w;
        outp[i] = o;
    }
}

// ---------------------------------------------------------------- output zero + readout
__global__ void k_zero_out(float* out) {
    if (threadIdx.x < 64) out[threadIdx.x] = 0.0f;
}

__global__ void k_readout(const float* __restrict__ w1, const float* __restrict__ b1v,
                          const float* __restrict__ w2, const float* __restrict__ b2v,
                          float* __restrict__ out) {
    __shared__ float s[HID];
    __shared__ float part[2];
    int n = blockIdx.x, t = threadIdx.x;   // 64 threads
    float h0 = g_h[n * HID + t];
    float h1 = g_h[n * HID + 64 + t];
    s[t]      = silu_f(h0);
    s[64 + t] = silu_f(h1);
    __syncthreads();
    float a = b1v[t];
    #pragma unroll 8
    for (int k = 0; k < HID; k++) a += s[k] * w1[k * 64 + t];
    float v = silu_f(a) * w2[t];
    #pragma unroll
    for (int off = 16; off > 0; off >>= 1) v += __shfl_down_sync(0xffffffffu, v, off);
    if ((t & 31) == 0) part[t >> 5] = v;
    __syncthreads();
    if (t == 0) atomicAdd(&out[n >> 7], part[0] + part[1] + b2v[0]);
}

// ---------------------------------------------------------------- launch
extern "C" void kernel_launch(void* const* d_in, const int* in_sizes, int n_in,
                              void* d_out, int out_size) {
    const int*   Z       = (const int*)  d_in[0];
    const float* pos     = (const float*)d_in[1];
    const int*   ei      = (const int*)  d_in[2];
    const float* embed_w = (const float*)d_in[3];
    const float* ew1     = (const float*)d_in[4];
    const float* eb1     = (const float*)d_in[5];
    const float* ew2     = (const float*)d_in[6];
    const float* eb2     = (const float*)d_in[7];
    const float* linw    = (const float*)d_in[8];
    const float* nw1     = (const float*)d_in[9];
    const float* nb1     = (const float*)d_in[10];
    const float* nw2     = (const float*)d_in[11];
    const float* nb2     = (const float*)d_in[12];
    const float* lng     = (const float*)d_in[13];
    const float* lnb     = (const float*)d_in[14];
    const float* row1    = (const float*)d_in[15];
    const float* rob1    = (const float*)d_in[16];
    const float* row2    = (const float*)d_in[17];
    const float* rob2    = (const float*)d_in[18];
    float* out = (float*)d_out;

    const int SM_TABLE = (64*64 + 64*128 + 128*128) * (int)sizeof(float);   // 112 KB
    const int SM_XGEMM = (64*128 + 128*128) * (int)sizeof(float);           //  96 KB
    const int SM_NODE  = (2*64*128 + 128*128) * (int)sizeof(float);         // 128 KB
    cudaFuncSetAttribute(k_table_f, cudaFuncAttributeMaxDynamicSharedMemorySize, SM_TABLE);
    cudaFuncSetAttribute(k_xgemm_f, cudaFuncAttributeMaxDynamicSharedMemorySize, SM_XGEMM);
    cudaFuncSetAttribute(k_node_f,  cudaFuncAttributeMaxDynamicSharedMemorySize, SM_NODE);

    k_embed<<<BN, HID>>>(Z, embed_w);
    k_dist<<<(NE + 255) / 256, 256>>>(ei, pos);
    dim3 tg(TLEN / 64, NBLK);
    k_table_f<<<tg, 256, SM_TABLE>>>(ew1, eb1, ew2, eb2);

    for (int b = 0; b < NBLK; b++) {
        k_xgemm_f<<<BN / 64, 256, SM_XGEMM>>>(linw + b * HID * HID);
        k_edge<<<NE / 8, 256>>>(ei, b);
        k_node_f<<<BN / 64, 256, SM_NODE>>>(
            nw1 + b * HID * HID, nb1 + b * HID,
            nw2 + b * HID * HID, nb2 + b * HID,
            lng + b * HID, lnb + b * HID);
    }

    k_zero_out<<<1, 64>>>(out);
    k_readout<<<BN, 64>>>(row1, rob1, row2, rob2, out);
}